// round 1
// baseline (speedup 1.0000x reference)
#include <cuda_runtime.h>
#include <math.h>

#define NN      2048            // nodes
#define DIM     512             // state dim
#define EDGE    8               // 2*E
#define GROWS   (EDGE * NN)     // 16384 gather rows
#define CAP     (1 << 20)       // CSR capacity (expected nnz ~503K)
#define NSTEPS  5

// ---------------- scratch (device globals; no allocation allowed) ----------
__device__ float d_h  [NN * DIM];        // 4 MB
__device__ float d_G  [GROWS * DIM];     // 32 MB   G[e,n,:] = sum_{m in A_e(n)} h[m,:]
__device__ float d_a  [NN * DIM];        // 4 MB
__device__ float d_z  [NN * DIM];        // 4 MB
__device__ float d_rh [NN * DIM];        // 4 MB
__device__ int   d_cnt   [GROWS];
__device__ float d_cntf  [GROWS];
__device__ int   d_rowptr[GROWS + 1];
__device__ int   d_colidx[CAP];          // 4 MB

// ---------------- CSR build (deterministic, ordered) -----------------------
// CSR row g = e*2048 + n scans adjacency[n, e*2048 .. e*2048+2048)
__global__ void csr_count(const float* __restrict__ adj) {
    int warp = (blockIdx.x * blockDim.x + threadIdx.x) >> 5;
    int lane = threadIdx.x & 31;
    if (warp >= GROWS) return;
    int e = warp >> 11;
    int n = warp & 2047;
    const float* base = adj + (size_t)n * 16384 + (size_t)e * 2048;
    int cnt = 0;
    for (int i = lane; i < 2048; i += 32) cnt += (base[i] != 0.0f);
    #pragma unroll
    for (int o = 16; o; o >>= 1) cnt += __shfl_down_sync(0xffffffffu, cnt, o);
    if (lane == 0) { d_cnt[warp] = cnt; d_cntf[warp] = (float)cnt; }
}

__global__ void csr_scan() {
    __shared__ int sh[1024];
    int tid = threadIdx.x;
    int pre[16];
    int run = 0;
    #pragma unroll
    for (int i = 0; i < 16; i++) { pre[i] = run; run += d_cnt[tid * 16 + i]; }
    sh[tid] = run;
    __syncthreads();
    for (int off = 1; off < 1024; off <<= 1) {
        int v = 0;
        if (tid >= off) v = sh[tid - off];
        __syncthreads();
        if (tid >= off) sh[tid] += v;
        __syncthreads();
    }
    int ex = sh[tid] - run;
    #pragma unroll
    for (int i = 0; i < 16; i++) d_rowptr[tid * 16 + i] = ex + pre[i];
    if (tid == 1023) d_rowptr[GROWS] = sh[1023];
}

__global__ void csr_fill(const float* __restrict__ adj) {
    int warp = (blockIdx.x * blockDim.x + threadIdx.x) >> 5;
    int lane = threadIdx.x & 31;
    if (warp >= GROWS) return;
    int e = warp >> 11;
    int n = warp & 2047;
    const float* base = adj + (size_t)n * 16384 + (size_t)e * 2048;
    int w = d_rowptr[warp];
    for (int i0 = 0; i0 < 2048; i0 += 32) {
        float v = base[i0 + lane];
        unsigned b = __ballot_sync(0xffffffffu, v != 0.0f);
        if (v != 0.0f) {
            int pos = w + __popc(b & ((1u << lane) - 1u));
            if (pos < CAP) d_colidx[pos] = i0 + lane;
        }
        w += __popc(b);
    }
}

// ---------------- h init: h[:, :256] = annotations, rest 0 -----------------
__global__ void init_h(const float* __restrict__ ann) {
    int idx = blockIdx.x * blockDim.x + threadIdx.x;
    if (idx >= NN * DIM) return;
    int n = idx >> 9, d = idx & 511;
    d_h[idx] = (d < 256) ? ann[n * 256 + d] : 0.0f;
}

// ---------------- gather: G[g,:] = sum_{j in csr(g)} h[colidx[j], :] -------
__global__ void gather_k() {
    int g = blockIdx.x;
    int c = threadIdx.x;                 // 128 threads: one float4 lane each
    int beg = d_rowptr[g];
    int end = d_rowptr[g + 1];
    if (end > CAP) end = CAP;
    const float4* hp = (const float4*)d_h;
    float4 acc = make_float4(0.f, 0.f, 0.f, 0.f);
    int j = beg;
    for (; j + 1 < end; j += 2) {
        int m0 = __ldg(&d_colidx[j]);
        int m1 = __ldg(&d_colidx[j + 1]);
        float4 v0 = hp[m0 * 128 + c];
        float4 v1 = hp[m1 * 128 + c];
        acc.x += v0.x; acc.y += v0.y; acc.z += v0.z; acc.w += v0.w;
        acc.x += v1.x; acc.y += v1.y; acc.z += v1.z; acc.w += v1.w;
    }
    if (j < end) {
        int m = __ldg(&d_colidx[j]);
        float4 v = hp[m * 128 + c];
        acc.x += v.x; acc.y += v.y; acc.z += v.z; acc.w += v.w;
    }
    ((float4*)d_G)[g * 128 + c] = acc;
}

// ---------------- fused GEMM -------------------------------------------------
// C[2048,512] = sum_s A_s[2048,512] @ B_s[512,512]   (+ mode-specific epilogue)
// asel: 0 -> A_s = d_G + s*NN*DIM (8 segs);  1 -> {d_a, d_h};  2 -> {d_a, d_rh}
// MODE 0: out=d_a;  acc += sum_e cntf[e,n]*b_prop[e,f]
// MODE 1: out=d_z;  sigmoid(acc+bias)
// MODE 2: out=d_rh; sigmoid(acc+bias) * h
// MODE 3: out=(out_ext? out_ext : d_h); ht=tanh(acc+bias); h' = h + z*(ht-h)
struct Ptr8 { const float* p[8]; };

__device__ __forceinline__ float sigmoidf_(float x) { return 1.0f / (1.0f + expf(-x)); }

template <int MODE>
__global__ void __launch_bounds__(256)
gemm_k(int asel, Ptr8 Bp, int nseg,
       const float* __restrict__ bias,    // [512] (modes 1-3)
       const float* __restrict__ bprop,   // [8,512] (mode 0)
       float* __restrict__ out_ext)       // mode 3 only (may be null)
{
    __shared__ float As[16][132];
    __shared__ float Bs[16][64];
    const int tid  = threadIdx.x;
    const int row0 = blockIdx.y * 128;
    const int col0 = blockIdx.x * 64;
    const int tx = tid & 15, ty = tid >> 4;
    const int trow = ty * 8, tcol = tx * 4;

    float acc[8][4];
    #pragma unroll
    for (int i = 0; i < 8; i++)
        #pragma unroll
        for (int j = 0; j < 4; j++) acc[i][j] = 0.0f;

    const int a_r = tid >> 2;
    const int a_k = (tid & 3) << 2;
    const int b_k = tid >> 4;
    const int b_c = (tid & 15) << 2;

    for (int s = 0; s < nseg; s++) {
        const float* A;
        if (asel == 0)      A = d_G + (size_t)s * (NN * DIM);
        else if (asel == 1) A = (s == 0) ? d_a : d_h;
        else                A = (s == 0) ? d_a : d_rh;
        const float* B = Bp.p[s];

        for (int kt = 0; kt < 512; kt += 16) {
            float4 av0 = *(const float4*)(A + (size_t)(row0 + a_r)      * 512 + kt + a_k);
            float4 av1 = *(const float4*)(A + (size_t)(row0 + a_r + 64) * 512 + kt + a_k);
            float4 bv  = *(const float4*)(B + (size_t)(kt + b_k)        * 512 + col0 + b_c);
            __syncthreads();
            As[a_k + 0][a_r] = av0.x; As[a_k + 1][a_r] = av0.y;
            As[a_k + 2][a_r] = av0.z; As[a_k + 3][a_r] = av0.w;
            As[a_k + 0][a_r + 64] = av1.x; As[a_k + 1][a_r + 64] = av1.y;
            As[a_k + 2][a_r + 64] = av1.z; As[a_k + 3][a_r + 64] = av1.w;
            *(float4*)&Bs[b_k][b_c] = bv;
            __syncthreads();
            #pragma unroll
            for (int k = 0; k < 16; k++) {
                float4 a0 = *(const float4*)&As[k][trow];
                float4 a1 = *(const float4*)&As[k][trow + 4];
                float4 b0 = *(const float4*)&Bs[k][tcol];
                float ar[8] = {a0.x, a0.y, a0.z, a0.w, a1.x, a1.y, a1.z, a1.w};
                float br[4] = {b0.x, b0.y, b0.z, b0.w};
                #pragma unroll
                for (int i = 0; i < 8; i++)
                    #pragma unroll
                    for (int j = 0; j < 4; j++)
                        acc[i][j] += ar[i] * br[j];
            }
        }
    }

    const int cbase = col0 + tcol;
    float4 bb = make_float4(0.f, 0.f, 0.f, 0.f);
    if (MODE != 0 && bias) bb = *(const float4*)(bias + cbase);

    if (MODE == 0) {
        #pragma unroll
        for (int e = 0; e < 8; e++) {
            float4 bp4 = *(const float4*)(bprop + e * 512 + cbase);
            #pragma unroll
            for (int i = 0; i < 8; i++) {
                float cf = d_cntf[e * 2048 + row0 + trow + i];
                acc[i][0] += cf * bp4.x; acc[i][1] += cf * bp4.y;
                acc[i][2] += cf * bp4.z; acc[i][3] += cf * bp4.w;
            }
        }
        #pragma unroll
        for (int i = 0; i < 8; i++) {
            size_t idx = (size_t)(row0 + trow + i) * 512 + cbase;
            *(float4*)(d_a + idx) = make_float4(acc[i][0], acc[i][1], acc[i][2], acc[i][3]);
        }
    } else if (MODE == 1) {
        #pragma unroll
        for (int i = 0; i < 8; i++) {
            size_t idx = (size_t)(row0 + trow + i) * 512 + cbase;
            float4 o;
            o.x = sigmoidf_(acc[i][0] + bb.x);
            o.y = sigmoidf_(acc[i][1] + bb.y);
            o.z = sigmoidf_(acc[i][2] + bb.z);
            o.w = sigmoidf_(acc[i][3] + bb.w);
            *(float4*)(d_z + idx) = o;
        }
    } else if (MODE == 2) {
        #pragma unroll
        for (int i = 0; i < 8; i++) {
            size_t idx = (size_t)(row0 + trow + i) * 512 + cbase;
            float4 hv = *(const float4*)(d_h + idx);
            float4 o;
            o.x = sigmoidf_(acc[i][0] + bb.x) * hv.x;
            o.y = sigmoidf_(acc[i][1] + bb.y) * hv.y;
            o.z = sigmoidf_(acc[i][2] + bb.z) * hv.z;
            o.w = sigmoidf_(acc[i][3] + bb.w) * hv.w;
            *(float4*)(d_rh + idx) = o;
        }
    } else {
        float* dst = out_ext ? out_ext : d_h;
        #pragma unroll
        for (int i = 0; i < 8; i++) {
            size_t idx = (size_t)(row0 + trow + i) * 512 + cbase;
            float4 zv = *(const float4*)(d_z + idx);
            float4 hv = *(const float4*)(d_h + idx);
            float4 o;
            float ht;
            ht = tanhf(acc[i][0] + bb.x); o.x = hv.x + zv.x * (ht - hv.x);
            ht = tanhf(acc[i][1] + bb.y); o.y = hv.y + zv.y * (ht - hv.y);
            ht = tanhf(acc[i][2] + bb.z); o.z = hv.z + zv.z * (ht - hv.z);
            ht = tanhf(acc[i][3] + bb.w); o.w = hv.w + zv.w * (ht - hv.w);
            *(float4*)(dst + idx) = o;
        }
    }
}

// ---------------- launch ----------------------------------------------------
extern "C" void kernel_launch(void* const* d_in, const int* in_sizes, int n_in,
                              void* d_out, int out_size) {
    const float* adj = (const float*)d_in[0];
    const float* ann = (const float*)d_in[1];
    const float* Wp  = (const float*)d_in[2];
    const float* bp  = (const float*)d_in[3];
    const float* Wz  = (const float*)d_in[4];
    const float* Uz  = (const float*)d_in[5];
    const float* bz  = (const float*)d_in[6];
    const float* Wr  = (const float*)d_in[7];
    const float* Ur  = (const float*)d_in[8];
    const float* br  = (const float*)d_in[9];
    const float* Wh  = (const float*)d_in[10];
    const float* Uh  = (const float*)d_in[11];
    const float* bh  = (const float*)d_in[12];
    float* out = (float*)d_out;

    csr_count<<<GROWS / 8, 256>>>(adj);
    csr_scan<<<1, 1024>>>();
    csr_fill<<<GROWS / 8, 256>>>(adj);
    init_h<<<(NN * DIM) / 256, 256>>>(ann);

    dim3 ggrid(DIM / 64, NN / 128);   // (8, 16)

    Ptr8 Bagg;
    for (int e = 0; e < 8; e++) Bagg.p[e] = Wp + (size_t)e * 512 * 512;
    Ptr8 Bz; Bz.p[0] = Wz; Bz.p[1] = Uz;
    Ptr8 Br; Br.p[0] = Wr; Br.p[1] = Ur;
    Ptr8 Bh; Bh.p[0] = Wh; Bh.p[1] = Uh;

    for (int step = 0; step < NSTEPS; step++) {
        gather_k<<<GROWS, 128>>>();
        gemm_k<0><<<ggrid, 256>>>(0, Bagg, 8, nullptr, bp, nullptr);   // a
        gemm_k<1><<<ggrid, 256>>>(1, Bz, 2, bz, nullptr, nullptr);     // z
        gemm_k<2><<<ggrid, 256>>>(1, Br, 2, br, nullptr, nullptr);     // rh = r*h
        gemm_k<3><<<ggrid, 256>>>(2, Bh, 2, bh, nullptr,
                                  (step == NSTEPS - 1) ? out : nullptr); // h update
    }
}

// round 3
// speedup vs baseline: 2.0881x; 2.0881x over previous
#include <cuda_runtime.h>
#include <cuda_bf16.h>
#include <cstdint>
#include <math.h>

#define NN      2048
#define DIM     512
#define EDGE    8
#define GROWS   (EDGE * NN)
#define CAP     (1 << 20)
#define NSTEPS  5

// ---------------- device scratch (no allocation allowed) -------------------
__device__ __align__(256) float d_h [NN * DIM];
__device__ __align__(256) float d_z [NN * DIM];
__device__ __align__(256) __nv_bfloat16 d_hh [NN * DIM], d_hl [NN * DIM];
__device__ __align__(256) __nv_bfloat16 d_ah [NN * DIM], d_al [NN * DIM];
__device__ __align__(256) __nv_bfloat16 d_rhh[NN * DIM], d_rhl[NN * DIM];
__device__ __align__(256) __nv_bfloat16 d_Gh [GROWS * DIM], d_Gl [GROWS * DIM];
__device__ __align__(256) __nv_bfloat16 d_Bagg_h[DIM * 4096], d_Bagg_l[DIM * 4096]; // [n=512][k=4096]
__device__ __align__(256) __nv_bfloat16 d_Bzr_h[1024 * 1024], d_Bzr_l[1024 * 1024]; // [n=1024][k=1024]
__device__ __align__(256) __nv_bfloat16 d_Bh_h [DIM * 1024],  d_Bh_l [DIM * 1024];  // [n=512][k=1024]
__device__ int   d_cnt   [GROWS];
__device__ float d_cntf  [GROWS];
__device__ int   d_rowptr[GROWS + 1];
__device__ int   d_colidx[CAP];

// ---------------- mma/ldmatrix helpers (baseline PTX, sm_80+) --------------
__device__ __forceinline__ void ldsm4(uint32_t* r, uint32_t addr) {
    asm volatile("ldmatrix.sync.aligned.m8n8.x4.shared.b16 {%0,%1,%2,%3}, [%4];"
        : "=r"(r[0]), "=r"(r[1]), "=r"(r[2]), "=r"(r[3]) : "r"(addr));
}
__device__ __forceinline__ void mma16816(float* d, const uint32_t* a, const uint32_t* b) {
    asm volatile("mma.sync.aligned.m16n8k16.row.col.f32.bf16.bf16.f32 "
        "{%0,%1,%2,%3}, {%4,%5,%6,%7}, {%8,%9}, {%0,%1,%2,%3};"
        : "+f"(d[0]), "+f"(d[1]), "+f"(d[2]), "+f"(d[3])
        : "r"(a[0]), "r"(a[1]), "r"(a[2]), "r"(a[3]), "r"(b[0]), "r"(b[1]));
}

__device__ __forceinline__ void store_hilo2(__nv_bfloat16* ph, __nv_bfloat16* pl,
                                            float v0, float v1) {
    __nv_bfloat16 h0 = __float2bfloat16(v0);
    __nv_bfloat16 h1 = __float2bfloat16(v1);
    __nv_bfloat16 l0 = __float2bfloat16(v0 - __bfloat162float(h0));
    __nv_bfloat16 l1 = __float2bfloat16(v1 - __bfloat162float(h1));
    *(__nv_bfloat162*)ph = __nv_bfloat162(h0, h1);
    *(__nv_bfloat162*)pl = __nv_bfloat162(l0, l1);
}

// ---------------- CSR build (verified round 1) ------------------------------
__global__ void csr_count(const float* __restrict__ adj) {
    int warp = (blockIdx.x * blockDim.x + threadIdx.x) >> 5;
    int lane = threadIdx.x & 31;
    if (warp >= GROWS) return;
    int e = warp >> 11, n = warp & 2047;
    const float* base = adj + (size_t)n * 16384 + (size_t)e * 2048;
    int cnt = 0;
    for (int i = lane; i < 2048; i += 32) cnt += (base[i] != 0.0f);
    #pragma unroll
    for (int o = 16; o; o >>= 1) cnt += __shfl_down_sync(0xffffffffu, cnt, o);
    if (lane == 0) { d_cnt[warp] = cnt; d_cntf[warp] = (float)cnt; }
}

__global__ void csr_scan() {
    __shared__ int sh[1024];
    int tid = threadIdx.x;
    int pre[16];
    int run = 0;
    #pragma unroll
    for (int i = 0; i < 16; i++) { pre[i] = run; run += d_cnt[tid * 16 + i]; }
    sh[tid] = run;
    __syncthreads();
    for (int off = 1; off < 1024; off <<= 1) {
        int v = 0;
        if (tid >= off) v = sh[tid - off];
        __syncthreads();
        if (tid >= off) sh[tid] += v;
        __syncthreads();
    }
    int ex = sh[tid] - run;
    #pragma unroll
    for (int i = 0; i < 16; i++) d_rowptr[tid * 16 + i] = ex + pre[i];
    if (tid == 1023) d_rowptr[GROWS] = sh[1023];
}

__global__ void csr_fill(const float* __restrict__ adj) {
    int warp = (blockIdx.x * blockDim.x + threadIdx.x) >> 5;
    int lane = threadIdx.x & 31;
    if (warp >= GROWS) return;
    int e = warp >> 11, n = warp & 2047;
    const float* base = adj + (size_t)n * 16384 + (size_t)e * 2048;
    int w = d_rowptr[warp];
    for (int i0 = 0; i0 < 2048; i0 += 32) {
        float v = base[i0 + lane];
        unsigned b = __ballot_sync(0xffffffffu, v != 0.0f);
        if (v != 0.0f) {
            int pos = w + __popc(b & ((1u << lane) - 1u));
            if (pos < CAP) d_colidx[pos] = i0 + lane;
        }
        w += __popc(b);
    }
}

// ---------------- init h + hi/lo -------------------------------------------
__global__ void init_h(const float* __restrict__ ann) {
    int idx = blockIdx.x * blockDim.x + threadIdx.x;
    if (idx >= NN * DIM) return;
    int n = idx >> 9, d = idx & 511;
    float v = (d < 256) ? ann[n * 256 + d] : 0.0f;
    d_h[idx] = v;
    __nv_bfloat16 h = __float2bfloat16(v);
    d_hh[idx] = h;
    d_hl[idx] = __float2bfloat16(v - __bfloat162float(h));
}

// ---------------- weight transpose+pack: dst[n][k] = src[k][n] -------------
template <int TGT>
__global__ void packT(const float* __restrict__ src, int Kstride, int nofs, int kofs) {
    __shared__ float t[32][33];
    int k0 = blockIdx.x * 32, n0 = blockIdx.y * 32;
    int tx = threadIdx.x, ty = threadIdx.y;   // (32,8)
    #pragma unroll
    for (int j = 0; j < 32; j += 8)
        t[ty + j][tx] = src[(size_t)(k0 + ty + j) * DIM + n0 + tx];
    __syncthreads();
    __nv_bfloat16 *dh, *dl;
    if (TGT == 0)      { dh = d_Bagg_h; dl = d_Bagg_l; }
    else if (TGT == 1) { dh = d_Bzr_h;  dl = d_Bzr_l;  }
    else               { dh = d_Bh_h;   dl = d_Bh_l;   }
    #pragma unroll
    for (int j = 0; j < 32; j += 8) {
        float v = t[tx][ty + j];
        size_t o = (size_t)(nofs + n0 + ty + j) * Kstride + kofs + k0 + tx;
        __nv_bfloat16 h = __float2bfloat16(v);
        dh[o] = h;
        dl[o] = __float2bfloat16(v - __bfloat162float(h));
    }
}

// ---------------- gather: G[g,:] = sum h[col,:]; write bf16 hi/lo ----------
__global__ void gather_k() {
    int g = blockIdx.x;
    int c = threadIdx.x;                  // 128 threads, 4 floats each
    int beg = d_rowptr[g];
    int end = d_rowptr[g + 1];
    if (end > CAP) end = CAP;
    const float4* hp = (const float4*)d_h;
    float4 acc = make_float4(0.f, 0.f, 0.f, 0.f);
    int j = beg;
    for (; j + 1 < end; j += 2) {
        int m0 = __ldg(&d_colidx[j]);
        int m1 = __ldg(&d_colidx[j + 1]);
        float4 v0 = hp[m0 * 128 + c];
        float4 v1 = hp[m1 * 128 + c];
        acc.x += v0.x; acc.y += v0.y; acc.z += v0.z; acc.w += v0.w;
        acc.x += v1.x; acc.y += v1.y; acc.z += v1.z; acc.w += v1.w;
    }
    if (j < end) {
        int m = __ldg(&d_colidx[j]);
        float4 v = hp[m * 128 + c];
        acc.x += v.x; acc.y += v.y; acc.z += v.z; acc.w += v.w;
    }
    size_t o = (size_t)g * DIM + c * 4;
    store_hilo2(d_Gh + o,     d_Gl + o,     acc.x, acc.y);
    store_hilo2(d_Gh + o + 2, d_Gl + o + 2, acc.z, acc.w);
}

// ---------------- warp-MMA GEMM ---------------------------------------------
// C[2048, N] = sum over 3 bf16-split products of sum_seg A_seg @ B_seg^T
// MODE 0 (AGG): A = G (8 segs), B = Bagg [512][4096]; epi: += cnt*b_prop -> a hi/lo
// MODE 1 (ZR) : A = {a,h},      B = Bzr [1024][1024]; epi: z / r*h
// MODE 2 (H)  : A = {a,rh},     B = Bh  [512][1024];  epi: GRU combine
__device__ __forceinline__ const __nv_bfloat16* segA(int mode, bool lo, int seg) {
    if (mode == 0) return (lo ? d_Gl : d_Gh) + (size_t)seg * (NN * DIM);
    if (mode == 1) return seg ? (lo ? d_hl : d_hh) : (lo ? d_al : d_ah);
    return seg ? (lo ? d_rhl : d_rhh) : (lo ? d_al : d_ah);
}
__device__ __forceinline__ const __nv_bfloat16* segB(int mode, bool lo) {
    if (mode == 0) return lo ? d_Bagg_l : d_Bagg_h;
    if (mode == 1) return lo ? d_Bzr_l : d_Bzr_h;
    return lo ? d_Bh_l : d_Bh_h;
}

template <int MODE>
__device__ __forceinline__ void g2r(int t, int row0, int col0, int nseg, int BK,
                                    int tid, uint4* ra, uint4* rb) {
    int split = t / (nseg * 8);
    int rem = t - split * (nseg * 8);
    int seg = rem >> 3, kti = rem & 7;
    const __nv_bfloat16* Ap = segA(MODE, split == 2, seg);
    const __nv_bfloat16* Bp = segB(MODE, split == 1);
    const char* Ab = (const char*)(Ap + (size_t)row0 * 512 + kti * 64);
    const char* Bb = (const char*)(Bp + (size_t)col0 * BK + seg * 512 + kti * 64);
    #pragma unroll
    for (int i = 0; i < 4; i++) {
        int c = tid + (i << 8);
        int r = c >> 3, kb = (c & 7) << 4;
        ra[i] = *(const uint4*)(Ab + (size_t)r * 1024 + kb);
    }
    #pragma unroll
    for (int i = 0; i < 2; i++) {
        int c = tid + (i << 8);
        int r = c >> 3, kb = (c & 7) << 4;
        rb[i] = *(const uint4*)(Bb + (size_t)r * (BK * 2) + kb);
    }
}

__device__ __forceinline__ void r2s(char* sm, int buf, int tid,
                                    const uint4* ra, const uint4* rb) {
    char* A = sm + buf * 16384;
    char* B = sm + 32768 + buf * 8192;
    #pragma unroll
    for (int i = 0; i < 4; i++) {
        int c = tid + (i << 8);
        int r = c >> 3, kb = (c & 7) << 4;
        int off = (r << 7) + kb;
        off ^= (off >> 3) & 0x70;
        *(uint4*)(A + off) = ra[i];
    }
    #pragma unroll
    for (int i = 0; i < 2; i++) {
        int c = tid + (i << 8);
        int r = c >> 3, kb = (c & 7) << 4;
        int off = (r << 7) + kb;
        off ^= (off >> 3) & 0x70;
        *(uint4*)(B + off) = rb[i];
    }
}

template <int MODE>
__global__ void __launch_bounds__(256)
mma_gemm(const float* __restrict__ bias1, const float* __restrict__ bias2,
         float* __restrict__ outF) {
    __shared__ __align__(1024) char sm[49152];   // A:2x16KB, B:2x8KB
    const int tid = threadIdx.x, lane = tid & 31, warp = tid >> 5;
    const int wm = warp >> 1, wn = warp & 1;     // 4 x 2 warps, warp tile 32x32
    const int row0 = blockIdx.y * 128, col0 = blockIdx.x * 64;
    const int nseg = (MODE == 0) ? 8 : 2;
    const int BK = (MODE == 0) ? 4096 : 1024;
    const int NT = 3 * nseg * 8;
    const uint32_t smb = (uint32_t)__cvta_generic_to_shared(sm);

    float acc[2][4][4];
    #pragma unroll
    for (int i = 0; i < 2; i++)
        #pragma unroll
        for (int j = 0; j < 4; j++)
            #pragma unroll
            for (int q = 0; q < 4; q++) acc[i][j][q] = 0.0f;

    // ldmatrix lane constants
    const uint32_t xmask = (uint32_t)(lane & 7) << 4;
    const int arow = lane & 15;
    const uint32_t ach0 = (uint32_t)(lane >> 4) << 4;
    const int brow = (lane & 7) + ((lane >> 4) << 3);
    const uint32_t bch0 = (uint32_t)((lane >> 3) & 1) << 4;

    uint4 ra[4], rb[2];
    g2r<MODE>(0, row0, col0, nseg, BK, tid, ra, rb);
    r2s((char*)sm, 0, tid, ra, rb);
    __syncthreads();

    for (int t = 0; t < NT; t++) {
        const int buf = t & 1;
        if (t + 1 < NT) g2r<MODE>(t + 1, row0, col0, nseg, BK, tid, ra, rb);

        const uint32_t A0 = smb + buf * 16384;
        const uint32_t B0 = smb + 32768 + buf * 8192;
        uint32_t aAddr0 = A0 + (uint32_t)(wm * 32 + arow) * 128;
        uint32_t aAddr1 = aAddr0 + 16 * 128;
        uint32_t bAddr0 = B0 + (uint32_t)(wn * 32 + brow) * 128;
        uint32_t bAddr1 = bAddr0 + 16 * 128;

        #pragma unroll
        for (int k16 = 0; k16 < 4; k16++) {
            uint32_t af[2][4], bt[2][4];
            uint32_t ak = (ach0 + k16 * 32) ^ xmask;
            uint32_t bk = (bch0 + k16 * 32) ^ xmask;
            ldsm4(af[0], aAddr0 + ak);
            ldsm4(af[1], aAddr1 + ak);
            ldsm4(bt[0], bAddr0 + bk);
            ldsm4(bt[1], bAddr1 + bk);
            #pragma unroll
            for (int i = 0; i < 2; i++) {
                mma16816(acc[i][0], af[i], &bt[0][0]);
                mma16816(acc[i][1], af[i], &bt[0][2]);
                mma16816(acc[i][2], af[i], &bt[1][0]);
                mma16816(acc[i][3], af[i], &bt[1][2]);
            }
        }

        if (t + 1 < NT) {
            r2s((char*)sm, (t + 1) & 1, tid, ra, rb);
            __syncthreads();
        }
    }

    // ---------------- epilogue ----------------
    #pragma unroll
    for (int i = 0; i < 2; i++) {
        #pragma unroll
        for (int hf = 0; hf < 2; hf++) {
            const int m = row0 + wm * 32 + i * 16 + (lane >> 2) + hf * 8;
            float cf[EDGE];
            if (MODE == 0) {
                #pragma unroll
                for (int e = 0; e < EDGE; e++) cf[e] = d_cntf[e * NN + m];
            }
            #pragma unroll
            for (int j = 0; j < 4; j++) {
                const int c = col0 + wn * 32 + j * 8 + (lane & 3) * 2;
                float v0 = acc[i][j][hf * 2 + 0];
                float v1 = acc[i][j][hf * 2 + 1];

                if (MODE == 0) {
                    #pragma unroll
                    for (int e = 0; e < EDGE; e++) {
                        v0 = fmaf(cf[e], __ldg(bias1 + e * DIM + c), v0);
                        v1 = fmaf(cf[e], __ldg(bias1 + e * DIM + c + 1), v1);
                    }
                    size_t o = (size_t)m * DIM + c;
                    store_hilo2(d_ah + o, d_al + o, v0, v1);
                } else if (MODE == 1) {
                    if (c < DIM) {
                        v0 = 1.0f / (1.0f + __expf(-(v0 + __ldg(bias1 + c))));
                        v1 = 1.0f / (1.0f + __expf(-(v1 + __ldg(bias1 + c + 1))));
                        *(float2*)(d_z + (size_t)m * DIM + c) = make_float2(v0, v1);
                    } else {
                        const int c2 = c - DIM;
                        size_t o = (size_t)m * DIM + c2;
                        float r0 = 1.0f / (1.0f + __expf(-(v0 + __ldg(bias2 + c2))));
                        float r1 = 1.0f / (1.0f + __expf(-(v1 + __ldg(bias2 + c2 + 1))));
                        float2 hv = *(const float2*)(d_h + o);
                        store_hilo2(d_rhh + o, d_rhl + o, r0 * hv.x, r1 * hv.y);
                    }
                } else {
                    size_t o = (size_t)m * DIM + c;
                    float ht0 = tanhf(v0 + __ldg(bias1 + c));
                    float ht1 = tanhf(v1 + __ldg(bias1 + c + 1));
                    float2 hv = *(const float2*)(d_h + o);
                    float2 zv = *(const float2*)(d_z + o);
                    float n0 = hv.x + zv.x * (ht0 - hv.x);
                    float n1 = hv.y + zv.y * (ht1 - hv.y);
                    float* dst = outF ? outF : d_h;
                    *(float2*)(dst + o) = make_float2(n0, n1);
                    store_hilo2(d_hh + o, d_hl + o, n0, n1);
                }
            }
        }
    }
}

// ---------------- launch ----------------------------------------------------
extern "C" void kernel_launch(void* const* d_in, const int* in_sizes, int n_in,
                              void* d_out, int out_size) {
    const float* adj = (const float*)d_in[0];
    const float* ann = (const float*)d_in[1];
    const float* Wp  = (const float*)d_in[2];
    const float* bp  = (const float*)d_in[3];
    const float* Wz  = (const float*)d_in[4];
    const float* Uz  = (const float*)d_in[5];
    const float* bz  = (const float*)d_in[6];
    const float* Wr  = (const float*)d_in[7];
    const float* Ur  = (const float*)d_in[8];
    const float* br  = (const float*)d_in[9];
    const float* Wh  = (const float*)d_in[10];
    const float* Uh  = (const float*)d_in[11];
    const float* bh  = (const float*)d_in[12];
    float* out = (float*)d_out;

    csr_count<<<GROWS / 8, 256>>>(adj);
    csr_scan<<<1, 1024>>>();
    csr_fill<<<GROWS / 8, 256>>>(adj);
    init_h<<<(NN * DIM) / 256, 256>>>(ann);

    dim3 pg(16, 16), pb(32, 8);
    for (int e = 0; e < 8; e++)
        packT<0><<<pg, pb>>>(Wp + (size_t)e * DIM * DIM, 4096, 0, e * 512);
    packT<1><<<pg, pb>>>(Wz, 1024, 0, 0);
    packT<1><<<pg, pb>>>(Uz, 1024, 0, 512);
    packT<1><<<pg, pb>>>(Wr, 1024, 512, 0);
    packT<1><<<pg, pb>>>(Ur, 1024, 512, 512);
    packT<2><<<pg, pb>>>(Wh, 1024, 0, 0);
    packT<2><<<pg, pb>>>(Uh, 1024, 0, 512);

    dim3 gAgg(8, 16), gZr(16, 16), gH(8, 16);
    for (int step = 0; step < NSTEPS; step++) {
        gather_k<<<GROWS, 128>>>();
        mma_gemm<0><<<gAgg, 256>>>(bp, nullptr, nullptr);
        mma_gemm<1><<<gZr,  256>>>(bz, br, nullptr);
        mma_gemm<2><<<gH,   256>>>(bh, nullptr,
                                   (step == NSTEPS - 1) ? out : nullptr);
    }
}

// round 4
// speedup vs baseline: 2.4417x; 1.1693x over previous
#include <cuda_runtime.h>
#include <cuda_bf16.h>
#include <cstdint>
#include <math.h>

#define NN      2048
#define DIM     512
#define EDGE    8
#define GROWS   (EDGE * NN)
#define CAP     (1 << 20)
#define NSTEPS  5

// ---------------- device scratch (no allocation allowed) -------------------
__device__ __align__(256) float d_h [NN * DIM];
__device__ __align__(256) float d_z [NN * DIM];
__device__ __align__(256) __nv_bfloat16 d_hh [NN * DIM], d_hl [NN * DIM];
__device__ __align__(256) __nv_bfloat16 d_ah [NN * DIM], d_al [NN * DIM];
__device__ __align__(256) __nv_bfloat16 d_rhh[NN * DIM], d_rhl[NN * DIM];
__device__ __align__(256) __nv_bfloat16 d_Gh [GROWS * DIM], d_Gl [GROWS * DIM];
__device__ __align__(256) __nv_bfloat16 d_Bagg_h[DIM * 4096], d_Bagg_l[DIM * 4096]; // [n=512][k=4096]
__device__ __align__(256) __nv_bfloat16 d_Bzr_h[1024 * 1024], d_Bzr_l[1024 * 1024]; // [n=1024][k=1024]
__device__ __align__(256) __nv_bfloat16 d_Bh_h [DIM * 1024],  d_Bh_l [DIM * 1024];  // [n=512][k=1024]
__device__ int   d_cnt   [GROWS];
__device__ float d_cntf  [GROWS];
__device__ int   d_rowptr[GROWS + 1];
__device__ int   d_colidx[CAP];

// ---------------- mma/ldmatrix/cp.async helpers (baseline PTX) -------------
__device__ __forceinline__ void ldsm4(uint32_t* r, uint32_t addr) {
    asm volatile("ldmatrix.sync.aligned.m8n8.x4.shared.b16 {%0,%1,%2,%3}, [%4];"
        : "=r"(r[0]), "=r"(r[1]), "=r"(r[2]), "=r"(r[3]) : "r"(addr));
}
__device__ __forceinline__ void mma16816(float* d, const uint32_t* a, const uint32_t* b) {
    asm volatile("mma.sync.aligned.m16n8k16.row.col.f32.bf16.bf16.f32 "
        "{%0,%1,%2,%3}, {%4,%5,%6,%7}, {%8,%9}, {%0,%1,%2,%3};"
        : "+f"(d[0]), "+f"(d[1]), "+f"(d[2]), "+f"(d[3])
        : "r"(a[0]), "r"(a[1]), "r"(a[2]), "r"(a[3]), "r"(b[0]), "r"(b[1]));
}
__device__ __forceinline__ void cpa16(uint32_t smaddr, const void* g) {
    asm volatile("cp.async.cg.shared.global [%0], [%1], 16;" :: "r"(smaddr), "l"(g));
}
#define CPA_COMMIT() asm volatile("cp.async.commit_group;")
#define CPA_WAIT2()  asm volatile("cp.async.wait_group 2;")

__device__ __forceinline__ void store_hilo2(__nv_bfloat16* ph, __nv_bfloat16* pl,
                                            float v0, float v1) {
    __nv_bfloat16 h0 = __float2bfloat16(v0);
    __nv_bfloat16 h1 = __float2bfloat16(v1);
    __nv_bfloat16 l0 = __float2bfloat16(v0 - __bfloat162float(h0));
    __nv_bfloat16 l1 = __float2bfloat16(v1 - __bfloat162float(h1));
    *(__nv_bfloat162*)ph = __nv_bfloat162(h0, h1);
    *(__nv_bfloat162*)pl = __nv_bfloat162(l0, l1);
}

// ---------------- CSR build (verified) --------------------------------------
__global__ void csr_count(const float* __restrict__ adj) {
    int warp = (blockIdx.x * blockDim.x + threadIdx.x) >> 5;
    int lane = threadIdx.x & 31;
    if (warp >= GROWS) return;
    int e = warp >> 11, n = warp & 2047;
    const float* base = adj + (size_t)n * 16384 + (size_t)e * 2048;
    int cnt = 0;
    for (int i = lane; i < 2048; i += 32) cnt += (base[i] != 0.0f);
    #pragma unroll
    for (int o = 16; o; o >>= 1) cnt += __shfl_down_sync(0xffffffffu, cnt, o);
    if (lane == 0) { d_cnt[warp] = cnt; d_cntf[warp] = (float)cnt; }
}

__global__ void csr_scan() {
    __shared__ int sh[1024];
    int tid = threadIdx.x;
    int pre[16];
    int run = 0;
    #pragma unroll
    for (int i = 0; i < 16; i++) { pre[i] = run; run += d_cnt[tid * 16 + i]; }
    sh[tid] = run;
    __syncthreads();
    for (int off = 1; off < 1024; off <<= 1) {
        int v = 0;
        if (tid >= off) v = sh[tid - off];
        __syncthreads();
        if (tid >= off) sh[tid] += v;
        __syncthreads();
    }
    int ex = sh[tid] - run;
    #pragma unroll
    for (int i = 0; i < 16; i++) d_rowptr[tid * 16 + i] = ex + pre[i];
    if (tid == 1023) d_rowptr[GROWS] = sh[1023];
}

__global__ void csr_fill(const float* __restrict__ adj) {
    int warp = (blockIdx.x * blockDim.x + threadIdx.x) >> 5;
    int lane = threadIdx.x & 31;
    if (warp >= GROWS) return;
    int e = warp >> 11, n = warp & 2047;
    const float* base = adj + (size_t)n * 16384 + (size_t)e * 2048;
    int w = d_rowptr[warp];
    for (int i0 = 0; i0 < 2048; i0 += 32) {
        float v = base[i0 + lane];
        unsigned b = __ballot_sync(0xffffffffu, v != 0.0f);
        if (v != 0.0f) {
            int pos = w + __popc(b & ((1u << lane) - 1u));
            if (pos < CAP) d_colidx[pos] = i0 + lane;
        }
        w += __popc(b);
    }
}

// ---------------- init h + hi/lo -------------------------------------------
__global__ void init_h(const float* __restrict__ ann) {
    int idx = blockIdx.x * blockDim.x + threadIdx.x;
    if (idx >= NN * DIM) return;
    int n = idx >> 9, d = idx & 511;
    float v = (d < 256) ? ann[n * 256 + d] : 0.0f;
    d_h[idx] = v;
    __nv_bfloat16 h = __float2bfloat16(v);
    d_hh[idx] = h;
    d_hl[idx] = __float2bfloat16(v - __bfloat162float(h));
}

// ---------------- weight transpose+pack: dst[n][k] = src[k][n] -------------
template <int TGT>
__global__ void packT(const float* __restrict__ src, int Kstride, int nofs, int kofs) {
    __shared__ float t[32][33];
    int k0 = blockIdx.x * 32, n0 = blockIdx.y * 32;
    int tx = threadIdx.x, ty = threadIdx.y;   // (32,8)
    #pragma unroll
    for (int j = 0; j < 32; j += 8)
        t[ty + j][tx] = src[(size_t)(k0 + ty + j) * DIM + n0 + tx];
    __syncthreads();
    __nv_bfloat16 *dh, *dl;
    if (TGT == 0)      { dh = d_Bagg_h; dl = d_Bagg_l; }
    else if (TGT == 1) { dh = d_Bzr_h;  dl = d_Bzr_l;  }
    else               { dh = d_Bh_h;   dl = d_Bh_l;   }
    #pragma unroll
    for (int j = 0; j < 32; j += 8) {
        float v = t[tx][ty + j];
        size_t o = (size_t)(nofs + n0 + ty + j) * Kstride + kofs + k0 + tx;
        __nv_bfloat16 h = __float2bfloat16(v);
        dh[o] = h;
        dl[o] = __float2bfloat16(v - __bfloat162float(h));
    }
}

// ---------------- gather: G[g,:] = sum h[col,:]; write bf16 hi/lo ----------
__global__ void gather_k() {
    int g = blockIdx.x;
    int c = threadIdx.x;
    int beg = d_rowptr[g];
    int end = d_rowptr[g + 1];
    if (end > CAP) end = CAP;
    const float4* hp = (const float4*)d_h;
    float4 acc = make_float4(0.f, 0.f, 0.f, 0.f);
    int j = beg;
    for (; j + 1 < end; j += 2) {
        int m0 = __ldg(&d_colidx[j]);
        int m1 = __ldg(&d_colidx[j + 1]);
        float4 v0 = hp[m0 * 128 + c];
        float4 v1 = hp[m1 * 128 + c];
        acc.x += v0.x; acc.y += v0.y; acc.z += v0.z; acc.w += v0.w;
        acc.x += v1.x; acc.y += v1.y; acc.z += v1.z; acc.w += v1.w;
    }
    if (j < end) {
        int m = __ldg(&d_colidx[j]);
        float4 v = hp[m * 128 + c];
        acc.x += v.x; acc.y += v.y; acc.z += v.z; acc.w += v.w;
    }
    size_t o = (size_t)g * DIM + c * 4;
    store_hilo2(d_Gh + o,     d_Gl + o,     acc.x, acc.y);
    store_hilo2(d_Gh + o + 2, d_Gl + o + 2, acc.z, acc.w);
}

// ---------------- warp-MMA GEMM with cp.async pipeline ----------------------
// MODE 0 (AGG): A = G (8 segs), B = Bagg [512][4096]; epi: += cnt*b_prop -> a hi/lo
// MODE 1 (ZR) : A = {a,h},      B = Bzr [1024][1024]; epi: z / r*h
// MODE 2 (H)  : A = {a,rh},     B = Bh  [512][1024];  epi: GRU combine
__device__ __forceinline__ const __nv_bfloat16* segA(int mode, bool lo, int seg) {
    if (mode == 0) return (lo ? d_Gl : d_Gh) + (size_t)seg * (NN * DIM);
    if (mode == 1) return seg ? (lo ? d_hl : d_hh) : (lo ? d_al : d_ah);
    return seg ? (lo ? d_rhl : d_rhh) : (lo ? d_al : d_ah);
}
__device__ __forceinline__ const __nv_bfloat16* segB(int mode, bool lo) {
    if (mode == 0) return lo ? d_Bagg_l : d_Bagg_h;
    if (mode == 1) return lo ? d_Bzr_l : d_Bzr_h;
    return lo ? d_Bh_l : d_Bh_h;
}

#define STAGES     4
#define STAGE_SZ   24576
#define SM_DYN     (STAGES * STAGE_SZ)   // 96 KB

template <int MODE>
__device__ __forceinline__ void load_tile_async(uint32_t stage_base, int t,
                                                int row0, int col0, int tid) {
    constexpr int nseg = (MODE == 0) ? 8 : 2;
    constexpr int BK   = (MODE == 0) ? 4096 : 1024;
    int split = t / (nseg * 8);
    int rem = t - split * (nseg * 8);
    int seg = rem >> 3, kti = rem & 7;
    const __nv_bfloat16* Ap = segA(MODE, split == 2, seg);
    const __nv_bfloat16* Bp = segB(MODE, split == 1);
    const char* Ab = (const char*)(Ap + (size_t)row0 * 512 + kti * 64);
    const char* Bb = (const char*)(Bp + (size_t)col0 * BK + seg * 512 + kti * 64);
    #pragma unroll
    for (int i = 0; i < 4; i++) {
        int c = tid + (i << 8);
        int r = c >> 3, kb = (c & 7) << 4;
        int off = (r << 7) + kb;
        off ^= (off >> 3) & 0x70;
        cpa16(stage_base + off, Ab + (size_t)r * 1024 + kb);
    }
    #pragma unroll
    for (int i = 0; i < 2; i++) {
        int c = tid + (i << 8);
        int r = c >> 3, kb = (c & 7) << 4;
        int off = (r << 7) + kb;
        off ^= (off >> 3) & 0x70;
        cpa16(stage_base + 16384 + off, Bb + (size_t)r * (BK * 2) + kb);
    }
}

template <int MODE>
__global__ void __launch_bounds__(256)
mma_gemm(const float* __restrict__ bias1, const float* __restrict__ bias2,
         float* __restrict__ outF) {
    extern __shared__ __align__(1024) char sm[];
    const int tid = threadIdx.x, lane = tid & 31, warp = tid >> 5;
    const int wm = warp >> 1, wn = warp & 1;     // 4 x 2 warps, warp tile 32x32
    const int row0 = blockIdx.y * 128, col0 = blockIdx.x * 64;
    constexpr int nseg = (MODE == 0) ? 8 : 2;
    constexpr int NT = 3 * nseg * 8;
    const uint32_t smb = (uint32_t)__cvta_generic_to_shared(sm);

    float acc[2][4][4];
    #pragma unroll
    for (int i = 0; i < 2; i++)
        #pragma unroll
        for (int j = 0; j < 4; j++)
            #pragma unroll
            for (int q = 0; q < 4; q++) acc[i][j][q] = 0.0f;

    // ldmatrix lane constants
    const uint32_t xmask = (uint32_t)(lane & 7) << 4;
    const int arow = lane & 15;
    const uint32_t ach0 = (uint32_t)(lane >> 4) << 4;
    const int brow = (lane & 7) + ((lane >> 4) << 3);
    const uint32_t bch0 = (uint32_t)((lane >> 3) & 1) << 4;

    // prologue: fill STAGES-1 stages
    #pragma unroll
    for (int p = 0; p < STAGES - 1; p++) {
        load_tile_async<MODE>(smb + p * STAGE_SZ, p, row0, col0, tid);
        CPA_COMMIT();
    }

    int buf = 0;
    for (int t = 0; t < NT; t++) {
        CPA_WAIT2();
        __syncthreads();

        const int nt = t + STAGES - 1;
        if (nt < NT) {
            int nbuf = buf + STAGES - 1;
            if (nbuf >= STAGES) nbuf -= STAGES;
            load_tile_async<MODE>(smb + nbuf * STAGE_SZ, nt, row0, col0, tid);
        }
        CPA_COMMIT();   // always commit (empty groups keep wait-count exact)

        const uint32_t A0 = smb + buf * STAGE_SZ;
        const uint32_t B0 = A0 + 16384;
        uint32_t aAddr0 = A0 + (uint32_t)(wm * 32 + arow) * 128;
        uint32_t aAddr1 = aAddr0 + 16 * 128;
        uint32_t bAddr0 = B0 + (uint32_t)(wn * 32 + brow) * 128;
        uint32_t bAddr1 = bAddr0 + 16 * 128;

        #pragma unroll
        for (int k16 = 0; k16 < 4; k16++) {
            uint32_t af[2][4], bt[2][4];
            uint32_t ak = (ach0 + k16 * 32) ^ xmask;
            uint32_t bk = (bch0 + k16 * 32) ^ xmask;
            ldsm4(af[0], aAddr0 + ak);
            ldsm4(af[1], aAddr1 + ak);
            ldsm4(bt[0], bAddr0 + bk);
            ldsm4(bt[1], bAddr1 + bk);
            #pragma unroll
            for (int i = 0; i < 2; i++) {
                mma16816(acc[i][0], af[i], &bt[0][0]);
                mma16816(acc[i][1], af[i], &bt[0][2]);
                mma16816(acc[i][2], af[i], &bt[1][0]);
                mma16816(acc[i][3], af[i], &bt[1][2]);
            }
        }

        if (++buf == STAGES) buf = 0;
    }

    // ---------------- epilogue ----------------
    #pragma unroll
    for (int i = 0; i < 2; i++) {
        #pragma unroll
        for (int hf = 0; hf < 2; hf++) {
            const int m = row0 + wm * 32 + i * 16 + (lane >> 2) + hf * 8;
            float cf[EDGE];
            if (MODE == 0) {
                #pragma unroll
                for (int e = 0; e < EDGE; e++) cf[e] = d_cntf[e * NN + m];
            }
            #pragma unroll
            for (int j = 0; j < 4; j++) {
                const int c = col0 + wn * 32 + j * 8 + (lane & 3) * 2;
                float v0 = acc[i][j][hf * 2 + 0];
                float v1 = acc[i][j][hf * 2 + 1];

                if (MODE == 0) {
                    #pragma unroll
                    for (int e = 0; e < EDGE; e++) {
                        v0 = fmaf(cf[e], __ldg(bias1 + e * DIM + c), v0);
                        v1 = fmaf(cf[e], __ldg(bias1 + e * DIM + c + 1), v1);
                    }
                    size_t o = (size_t)m * DIM + c;
                    store_hilo2(d_ah + o, d_al + o, v0, v1);
                } else if (MODE == 1) {
                    if (c < DIM) {
                        v0 = 1.0f / (1.0f + __expf(-(v0 + __ldg(bias1 + c))));
                        v1 = 1.0f / (1.0f + __expf(-(v1 + __ldg(bias1 + c + 1))));
                        *(float2*)(d_z + (size_t)m * DIM + c) = make_float2(v0, v1);
                    } else {
                        const int c2 = c - DIM;
                        size_t o = (size_t)m * DIM + c2;
                        float r0 = 1.0f / (1.0f + __expf(-(v0 + __ldg(bias2 + c2))));
                        float r1 = 1.0f / (1.0f + __expf(-(v1 + __ldg(bias2 + c2 + 1))));
                        float2 hv = *(const float2*)(d_h + o);
                        store_hilo2(d_rhh + o, d_rhl + o, r0 * hv.x, r1 * hv.y);
                    }
                } else {
                    size_t o = (size_t)m * DIM + c;
                    float ht0 = tanhf(v0 + __ldg(bias1 + c));
                    float ht1 = tanhf(v1 + __ldg(bias1 + c + 1));
                    float2 hv = *(const float2*)(d_h + o);
                    float2 zv = *(const float2*)(d_z + o);
                    float n0 = hv.x + zv.x * (ht0 - hv.x);
                    float n1 = hv.y + zv.y * (ht1 - hv.y);
                    float* dst = outF ? outF : d_h;
                    *(float2*)(dst + o) = make_float2(n0, n1);
                    store_hilo2(d_hh + o, d_hl + o, n0, n1);
                }
            }
        }
    }
}

// ---------------- launch ----------------------------------------------------
extern "C" void kernel_launch(void* const* d_in, const int* in_sizes, int n_in,
                              void* d_out, int out_size) {
    const float* adj = (const float*)d_in[0];
    const float* ann = (const float*)d_in[1];
    const float* Wp  = (const float*)d_in[2];
    const float* bp  = (const float*)d_in[3];
    const float* Wz  = (const float*)d_in[4];
    const float* Uz  = (const float*)d_in[5];
    const float* bz  = (const float*)d_in[6];
    const float* Wr  = (const float*)d_in[7];
    const float* Ur  = (const float*)d_in[8];
    const float* br  = (const float*)d_in[9];
    const float* Wh  = (const float*)d_in[10];
    const float* Uh  = (const float*)d_in[11];
    const float* bh  = (const float*)d_in[12];
    float* out = (float*)d_out;

    cudaFuncSetAttribute(mma_gemm<0>, cudaFuncAttributeMaxDynamicSharedMemorySize, SM_DYN);
    cudaFuncSetAttribute(mma_gemm<1>, cudaFuncAttributeMaxDynamicSharedMemorySize, SM_DYN);
    cudaFuncSetAttribute(mma_gemm<2>, cudaFuncAttributeMaxDynamicSharedMemorySize, SM_DYN);

    csr_count<<<GROWS / 8, 256>>>(adj);
    csr_scan<<<1, 1024>>>();
    csr_fill<<<GROWS / 8, 256>>>(adj);
    init_h<<<(NN * DIM) / 256, 256>>>(ann);

    dim3 pg(16, 16), pb(32, 8);
    for (int e = 0; e < 8; e++)
        packT<0><<<pg, pb>>>(Wp + (size_t)e * DIM * DIM, 4096, 0, e * 512);
    packT<1><<<pg, pb>>>(Wz, 1024, 0, 0);
    packT<1><<<pg, pb>>>(Uz, 1024, 0, 512);
    packT<1><<<pg, pb>>>(Wr, 1024, 512, 0);
    packT<1><<<pg, pb>>>(Ur, 1024, 512, 512);
    packT<2><<<pg, pb>>>(Wh, 1024, 0, 0);
    packT<2><<<pg, pb>>>(Uh, 1024, 0, 512);

    dim3 gAgg(8, 16), gZr(16, 16), gH(8, 16);
    for (int step = 0; step < NSTEPS; step++) {
        gather_k<<<GROWS, 128>>>();
        mma_gemm<0><<<gAgg, 256, SM_DYN>>>(bp, nullptr, nullptr);
        mma_gemm<1><<<gZr,  256, SM_DYN>>>(bz, br, nullptr);
        mma_gemm<2><<<gH,   256, SM_DYN>>>(bh, nullptr,
                                           (step == NSTEPS - 1) ? out : nullptr);
    }
}